// round 11
// baseline (speedup 1.0000x reference)
#include <cuda_runtime.h>
#include <cuda_fp16.h>
#include <cstdint>

#define Bsz 256
#define Lsz 500
#define Dsz 3
#define Csz 32
#define Isz 35
#define Hsz 512
#define Msz 5
#define Osz 15
#define Jsz 35
#define NC  50
#define LC  10
#define BH  (Bsz*Hsz)   /* 131072 */
#define NSL 4           /* h slices (k_sums only) */
#define HS  (Hsz/NSL)   /* 128 */
#define BT  128         /* b tile (k_sums) */
#define NBT (Bsz/BT)    /* 2 */
#define XP  44          /* xs row stride (floats), k_sums */
#define NT  512

#define WCNT (Isz*HS)   /* 4480 */
#define XCNT (BT*XP)    /* 5632 */

/* ---- k_all v2 geometry ---- */
#define BT2  64         /* b tile */
#define NBT2 (Bsz/BT2)  /* 4 */
#define HPAD 260        /* hs row stride in u32 (256 half2 + pad) */
#define CPAD 520        /* cs row stride in halfs */
#define RSTR 42         /* red row stride (floats), bank-skewed */
#define SM2_HS  0                         /* u32 [64][260]  = 66560 B */
#define SM2_VS  66560                     /* u32 [256][40]  = 40960 B */
#define SM2_CS  107520                    /* half [64][520] = 66560 B */
#define SM2_RED 174080                    /* f32 [3][64][42]= 32256 B */
#define SM2_TOT 206336

// ONE extern dynamic-smem symbol for the whole TU
extern __shared__ __align__(16) char dyn_smem[];

// Scratch
__device__ __align__(16) float  g_S[(size_t)NC * BH];
__device__ __align__(16) float  g_P[(size_t)NC * BH];
__device__ __align__(16) __half g_c16[(size_t)Lsz * BH];

using u64 = unsigned long long;

__device__ __forceinline__ u64 splat2(float x) {
    u64 r; unsigned u = __float_as_uint(x);
    asm("mov.b64 %0, {%1, %1};" : "=l"(r) : "r"(u));
    return r;
}
__device__ __forceinline__ u64 fma2(u64 a, u64 b, u64 c) {
    u64 d; asm("fma.rn.f32x2 %0, %1, %2, %3;" : "=l"(d) : "l"(a), "l"(b), "l"(c));
    return d;
}
__device__ __forceinline__ u64 add2(u64 a, u64 b) {
    u64 d; asm("add.rn.f32x2 %0, %1, %2;" : "=l"(d) : "l"(a), "l"(b));
    return d;
}
__device__ __forceinline__ void cp16(unsigned dst, const void* src) {
    asm volatile("cp.async.ca.shared.global [%0], [%1], 16;" :: "r"(dst), "l"(src));
}
__device__ __forceinline__ void cp4(unsigned dst, const void* src) {
    asm volatile("cp.async.ca.shared.global [%0], [%1], 4;" :: "r"(dst), "l"(src));
}
__device__ __forceinline__ void cp_commit() { asm volatile("cp.async.commit_group;"); }
__device__ __forceinline__ void cp_wait0()  { asm volatile("cp.async.wait_group 0;"); }

// m16n8k16 fp16 HMMA with fp32 accumulate (sm_80 PTX; valid on sm_103 target)
__device__ __forceinline__ void mma_f16(float d[4],
                                        unsigned a0, unsigned a1, unsigned a2, unsigned a3,
                                        unsigned b0, unsigned b1) {
    asm volatile(
        "mma.sync.aligned.m16n8k16.row.col.f32.f16.f16.f32 "
        "{%0,%1,%2,%3}, {%4,%5,%6,%7}, {%8,%9}, {%0,%1,%2,%3};"
        : "+f"(d[0]), "+f"(d[1]), "+f"(d[2]), "+f"(d[3])
        : "r"(a0), "r"(a1), "r"(a2), "r"(a3), "r"(b0), "r"(b1));
}

// ---------------------------------------------------------------------------
// k_sums: the encoder, fp32 chunk sums + fp16 c store. (unchanged, known-good)
// ---------------------------------------------------------------------------
__device__ __forceinline__ void stage_wx_async(unsigned ws_a, unsigned xs_a,
                                               const float* __restrict__ W,
                                               const float* __restrict__ inp,
                                               const float* __restrict__ zz,
                                               int l, int h0, int b0, int tid)
{
    const float4* wsrc = (const float4*)(W + (size_t)l * (Isz * Hsz)) + (h0 >> 2);
#pragma unroll
    for (int q = 0; q < 3; q++) {
        int idx = tid + NT * q;
        if (idx < Isz * 32) {
            int row = idx >> 5, col = idx & 31;
            cp16(ws_a + (unsigned)(row * 32 + col) * 16, wsrc + row * 128 + col);
        }
    }
#pragma unroll
    for (int q = 0; q < 2; q++) {
        int idx = tid + NT * q;
        int b = idx >> 3, qf = idx & 7;
        cp16(xs_a + (unsigned)(b * XP + 4 + qf * 4) * 4,
             zz + (size_t)(b0 + b) * (Lsz * Csz) + (size_t)l * Csz + qf * 4);
    }
    if (tid < BT * Dsz) {
        int b = tid / Dsz, i = tid % Dsz;
        cp4(xs_a + (unsigned)(b * XP + i) * 4,
            inp + (size_t)(b0 + b) * (Lsz * Dsz) + (size_t)l * Dsz + i);
    }
}

__device__ __forceinline__ void encode_step(u64 c2[4][4], const float* ws,
                                            const float* xs, int bg, int hg)
{
#pragma unroll
    for (int r = 0; r < 4; r++)
#pragma unroll
        for (int p = 0; p < 4; p++) c2[r][p] = 0ull;
#pragma unroll
    for (int i = 0; i < Isz; i++) {
        const int xc = (i < Dsz) ? i : i + 1;
        u64 xa[4], wv[4];
#pragma unroll
        for (int r = 0; r < 4; r++) xa[r] = splat2(xs[(bg * 4 + r) * XP + xc]);
#pragma unroll
        for (int p = 0; p < 4; p++) wv[p] = *(const u64*)&ws[i * HS + hg * 2 + 32 * p];
#pragma unroll
        for (int r = 0; r < 4; r++)
#pragma unroll
            for (int p = 0; p < 4; p++) c2[r][p] = fma2(xa[r], wv[p], c2[r][p]);
    }
}

__global__ void __launch_bounds__(NT) k_sums(const float* __restrict__ inp,
                                             const float* __restrict__ zz,
                                             const float* __restrict__ W)
{
    float* smem = (float*)dyn_smem;
    float* ws[2] = { smem, smem + WCNT };
    float* xs[2] = { smem + 2 * WCNT, smem + 2 * WCNT + XCNT };
    const unsigned sbase = (unsigned)__cvta_generic_to_shared(dyn_smem);
    const unsigned ws_a[2] = { sbase, sbase + WCNT * 4u };
    const unsigned xs_a[2] = { sbase + 2u * WCNT * 4u, sbase + (2u * WCNT + XCNT) * 4u };

    const int tid = threadIdx.x;
    const int b0  = (blockIdx.x / NSL) * BT;
    const int h0  = (blockIdx.x % NSL) * HS;
    const int k   = blockIdx.y;
    const int bg  = tid >> 4, hg = tid & 15;

    u64 acc[4][4];
#pragma unroll
    for (int r = 0; r < 4; r++)
#pragma unroll
        for (int p = 0; p < 4; p++) acc[r][p] = 0ull;

    stage_wx_async(ws_a[0], xs_a[0], W, inp, zz, k * LC, h0, b0, tid);
    cp_commit(); cp_wait0();
    __syncthreads();

    for (int t = 0; t < LC; t++) {
        const int l = k * LC + t;
        const int cur = t & 1, nxt = cur ^ 1;
        if (t + 1 < LC) {
            stage_wx_async(ws_a[nxt], xs_a[nxt], W, inp, zz, l + 1, h0, b0, tid);
            cp_commit();
        }
        u64 c2[4][4];
        encode_step(c2, ws[cur], xs[cur], bg, hg);
#pragma unroll
        for (int r = 0; r < 4; r++) {
            __half* crow = g_c16 + ((size_t)l * Bsz + b0 + bg * 4 + r) * Hsz + h0;
#pragma unroll
            for (int p = 0; p < 4; p++) {
                acc[r][p] = add2(acc[r][p], c2[r][p]);
                float2 f = *(float2*)&c2[r][p];
                *(__half2*)&crow[hg * 2 + 32 * p] = __floats2half2_rn(f.x, f.y);
            }
        }
        cp_wait0();
        __syncthreads();
    }

    float* sb = g_S + (size_t)k * BH + (size_t)b0 * Hsz + h0;
#pragma unroll
    for (int r = 0; r < 4; r++)
#pragma unroll
        for (int p = 0; p < 4; p++)
            *(u64*)&sb[(size_t)(bg * 4 + r) * Hsz + hg * 2 + 32 * p] = acc[r][p];
}

__global__ void k_scan(const float* __restrict__ benc)
{
    const int idx = blockIdx.x * 256 + threadIdx.x;
    float run = benc[idx & (Hsz - 1)];
#pragma unroll 5
    for (int k = 0; k < NC; k++) {
        g_P[(size_t)k * BH + idx] = run;
        run += g_S[(size_t)k * BH + idx];
    }
}

// ---------------------------------------------------------------------------
// k_all v2: full-H prefix + fp16 HMMA decode, direct output (+bias).
// Block = (64-b tile, chunk); grid (4, 50) = 200. 512 threads = 16 warps:
//   mma map: sb = wid&3 (16-row b strip), kq = wid>>2 (128-h K quarter).
//   acc map: thread owns 2 b x 32 h (bg = tid>>4, hg = tid&15), 64 fp32 regs.
// Per step: [MMA from hs/vs; acc += c16 from cs] sync [kq>0 wrote red; kq0
// sums quarters + bias -> out; publish relu(acc)->hs fp16; STS vs(l+1);
// cp.async cs<-c16(l+1)] wait, sync. Single-buffered cs/vs (phase-separated).
// ---------------------------------------------------------------------------
__global__ void __launch_bounds__(NT) k_all(const float* __restrict__ Vmu,
                                            const float* __restrict__ Vsg,
                                            const float* __restrict__ Vpi,
                                            const float* __restrict__ bmu,
                                            const float* __restrict__ bsg,
                                            const float* __restrict__ bpi,
                                            float* __restrict__ out)
{
    char* smem = dyn_smem;
    const unsigned sbase = (unsigned)__cvta_generic_to_shared(dyn_smem);
    unsigned* hs = (unsigned*)(smem + SM2_HS);    // relu(a) half2 [64][260]
    unsigned* vs = (unsigned*)(smem + SM2_VS);    // V half2 [256][40]
    __half*   cs = (__half*)(smem + SM2_CS);      // c16 [64][520]
    float*    red = (float*)(smem + SM2_RED);     // [3][64][42]
    const unsigned cs_a = sbase + SM2_CS;

    const int tid = threadIdx.x;
    const int wid = tid >> 5, lane = tid & 31;
    const int b0  = blockIdx.x * BT2;
    const int k   = blockIdx.y;
    const int bg  = tid >> 4, hg = tid & 15;     // acc owner: 2b x 32h
    const int sb  = wid & 3,  kq = wid >> 2;     // mma: b strip x K quarter
    const int rq  = lane >> 2, kl = lane & 3;
    const int rb  = sb * 16 + rq;                // D fragment row (0..55, +8)
    const int l0  = k * LC;

    // V load descriptors (loop-invariant): tag<<30 | base offset of row 2*h2
    // u = tid + 512q -> h2 = u/40 (0..255), jc = u%40
    unsigned vq[20];
#pragma unroll
    for (int q = 0; q < 20; q++) {
        int u = tid + NT * q;
        int h2 = u / 40, jc = u % 40;
        unsigned tag, off;
        if (jc < 15)      { tag = 0u; off = (2 * h2) * Osz + jc; }
        else if (jc < 30) { tag = 1u; off = (2 * h2) * Osz + (jc - 15); }
        else if (jc < 35) { tag = 2u; off = (2 * h2) * Msz + (jc - 30); }
        else              { tag = 3u; off = 0; }
        vq[q] = (tag << 30) | off;
    }

    auto load_V = [&](int l, unsigned vreg[20]) {
        const size_t lmu = (size_t)l * (Hsz * Osz);
        const size_t lpi = (size_t)l * (Hsz * Msz);
#pragma unroll
        for (int q = 0; q < 20; q++) {
            unsigned tag = vq[q] >> 30, off = vq[q] & 0x3FFFFFFFu;
            float v0 = 0.0f, v1 = 0.0f;
            if (tag == 0u)      { v0 = Vmu[lmu + off]; v1 = Vmu[lmu + off + Osz]; }
            else if (tag == 1u) { v0 = Vsg[lmu + off]; v1 = Vsg[lmu + off + Osz]; }
            else if (tag == 2u) { v0 = Vpi[lpi + off]; v1 = Vpi[lpi + off + Msz]; }
            __half2 h2v = __floats2half2_rn(v0, v1);
            vreg[q] = *(unsigned*)&h2v;
        }
    };
    auto stage_cs = [&](int l) {   // 64 rows x 1024 B, 4096 cp16
#pragma unroll
        for (int q = 0; q < 8; q++) {
            int idx = tid + NT * q;
            int row = idx >> 6, ch = idx & 63;
            cp16(cs_a + (unsigned)(row * CPAD * 2 + ch * 16),
                 g_c16 + ((size_t)l * Bsz + b0 + row) * Hsz + ch * 8);
        }
        cp_commit();
    };
    auto publish_A = [&](u64 acc[2][16]) {
#pragma unroll
        for (int r = 0; r < 2; r++) {
            const int b = bg * 2 + r;
#pragma unroll
            for (int p = 0; p < 16; p++) {
                float2 v = *(float2*)&acc[r][p];
                __half2 h2v = __floats2half2_rn(fmaxf(v.x, 0.0f), fmaxf(v.y, 0.0f));
                hs[b * HPAD + hg + 16 * p] = *(unsigned*)&h2v;
            }
        }
    };

    // ---- prologue: stage c16[l0], V[l0]; init acc from carry P; publish
    stage_cs(l0);
    {
        unsigned v0[20];
        load_V(l0, v0);
#pragma unroll
        for (int q = 0; q < 20; q++) vs[tid + NT * q] = v0[q];
    }
    u64 acc[2][16];
    {
        const float* P = g_P + (size_t)k * BH + (size_t)b0 * Hsz;
#pragma unroll
        for (int r = 0; r < 2; r++)
#pragma unroll
            for (int p = 0; p < 16; p++) {
                float2 v = *(const float2*)&P[(size_t)(bg * 2 + r) * Hsz + hg * 2 + 32 * p];
                acc[r][p] = *(const u64*)&v;
            }
    }
    publish_A(acc);
    cp_wait0();
    __syncthreads();

    for (int t = 0; t < LC; t++) {
        const int l = l0 + t;

        // issue next-step V loads early (latency hidden under MMA)
        unsigned vreg[20];
        if (t + 1 < LC) load_V(l + 1, vreg);

        // ---- (A) MMA: D[16b x 40j] over this warp's 128-h quarter
        float d[5][4];
#pragma unroll
        for (int n = 0; n < 5; n++)
#pragma unroll
            for (int u = 0; u < 4; u++) d[n][u] = 0.0f;

#pragma unroll
        for (int kc = 0; kc < 8; kc++) {
            const int k0h = kq * 64 + kc * 8;   // half2 k index
            unsigned a0 = hs[rb * HPAD + k0h + kl];
            unsigned a1 = hs[(rb + 8) * HPAD + k0h + kl];
            unsigned a2 = hs[rb * HPAD + k0h + 4 + kl];
            unsigned a3 = hs[(rb + 8) * HPAD + k0h + 4 + kl];
#pragma unroll
            for (int n = 0; n < 5; n++) {
                unsigned bf0 = vs[(k0h + kl) * 40 + n * 8 + rq];
                unsigned bf1 = vs[(k0h + 4 + kl) * 40 + n * 8 + rq];
                mma_f16(d[n], a0, a1, a2, a3, bf0, bf1);
            }
        }

        // ---- (B) recurrence: acc += c16[l] (cs resident)
#pragma unroll
        for (int r = 0; r < 2; r++)
#pragma unroll
            for (int p = 0; p < 16; p++) {
                __half2 h2v = *(const __half2*)&cs[(bg * 2 + r) * CPAD + hg * 2 + 32 * p];
                float2 c = __half22float2(h2v);
                float2 a = *(float2*)&acc[r][p];
                a.x += c.x; a.y += c.y;
                acc[r][p] = *(u64*)&a;
            }

        // ---- (C) K quarters 1..3 publish partials
        if (kq) {
            float* rq_base = red + (kq - 1) * (BT2 * RSTR);
#pragma unroll
            for (int n = 0; n < 5; n++) {
                const int j = n * 8 + 2 * kl;
                *(float2*)&rq_base[rb * RSTR + j]       = make_float2(d[n][0], d[n][1]);
                *(float2*)&rq_base[(rb + 8) * RSTR + j] = make_float2(d[n][2], d[n][3]);
            }
        }
        __syncthreads();

        // ---- (D) K quarter 0 sums + bias + stores out
        if (!kq) {
#pragma unroll
            for (int n = 0; n < 5; n++) {
                const int j = n * 8 + 2 * kl;
                float2 s0 = make_float2(d[n][0], d[n][1]);
                float2 s1 = make_float2(d[n][2], d[n][3]);
#pragma unroll
                for (int q2 = 0; q2 < 3; q2++) {
                    float2 r0 = *(float2*)&red[q2 * (BT2 * RSTR) + rb * RSTR + j];
                    float2 r1 = *(float2*)&red[q2 * (BT2 * RSTR) + (rb + 8) * RSTR + j];
                    s0.x += r0.x; s0.y += r0.y;
                    s1.x += r1.x; s1.y += r1.y;
                }
                float bj0 = (j < 15) ? bmu[l * Osz + j]
                          : (j < 30) ? bsg[l * Osz + (j - 15)]
                          : (j < 35) ? bpi[l * Msz + (j - 30)] : 0.0f;
                float bj1 = (j + 1 < 15) ? bmu[l * Osz + j + 1]
                          : (j + 1 < 30) ? bsg[l * Osz + (j + 1 - 15)]
                          : (j + 1 < 35) ? bpi[l * Msz + (j + 1 - 30)] : 0.0f;
                float* o0 = out + ((size_t)(b0 + rb) * Lsz + l) * Jsz;
                float* o1 = out + ((size_t)(b0 + rb + 8) * Lsz + l) * Jsz;
                if (j < 35)     { o0[j] = s0.x + bj0;     o1[j] = s1.x + bj0; }
                if (j + 1 < 35) { o0[j + 1] = s0.y + bj1; o1[j + 1] = s1.y + bj1; }
            }
        }

        // ---- (E/F/G) publish relu(a[l+1]); restage vs/cs for next step
        if (t + 1 < LC) {
            publish_A(acc);
#pragma unroll
            for (int q = 0; q < 20; q++) vs[tid + NT * q] = vreg[q];
            stage_cs(l + 1);
            cp_wait0();
        }
        __syncthreads();
    }
}

// ---------------------------------------------------------------------------
extern "C" void kernel_launch(void* const* d_in, const int* in_sizes, int n_in,
                              void* d_out, int out_size)
{
    const float* inp  = (const float*)d_in[0];
    const float* zz   = (const float*)d_in[1];
    const float* W    = (const float*)d_in[2];
    const float* benc = (const float*)d_in[3];
    const float* Vmu  = (const float*)d_in[4];
    const float* bmu  = (const float*)d_in[5];
    const float* Vsg  = (const float*)d_in[6];
    const float* bsg  = (const float*)d_in[7];
    const float* Vpi  = (const float*)d_in[8];
    const float* bpi  = (const float*)d_in[9];
    float* out = (float*)d_out;

    const int sm1 = (2 * WCNT + 2 * XCNT) * (int)sizeof(float);   // 80.9 KB
    cudaFuncSetAttribute(k_sums, cudaFuncAttributeMaxDynamicSharedMemorySize, sm1);
    cudaFuncSetAttribute(k_all,  cudaFuncAttributeMaxDynamicSharedMemorySize, SM2_TOT);

    k_sums<<<dim3(NBT * NSL, NC), NT, sm1>>>(inp, zz, W);
    k_scan<<<BH / 256, 256>>>(benc);
    k_all <<<dim3(NBT2, NC), NT, SM2_TOT>>>(Vmu, Vsg, Vpi, bmu, bsg, bpi, out);
}

// round 12
// speedup vs baseline: 1.2927x; 1.2927x over previous
#include <cuda_runtime.h>
#include <cuda_fp16.h>
#include <cstdint>

#define Bsz 256
#define Lsz 500
#define Dsz 3
#define Csz 32
#define Isz 35
#define Hsz 512
#define Msz 5
#define Osz 15
#define Jsz 35
#define NC  50
#define LC  10
#define BH  (Bsz*Hsz)   /* 131072 */
#define BL  (Bsz*Lsz)   /* 128000 */
#define NSL 4           /* h slices */
#define HS  (Hsz/NSL)   /* 128 */
#define BT  128         /* b tile (k_all) */
#define NBT (Bsz/BT)    /* 2 */
#define BTS 64          /* b tile (k_sums) */
#define NBTS (Bsz/BTS)  /* 4 */
#define XP  44          /* xs row stride (floats), k_sums */
#define NT  512
#define CP  136         /* c16 smem row stride (halfs) */
#define HP2 132         /* hs row stride (words) */

#define WCNT (Isz*HS)   /* 4480 */
#define XCNT (BTS*XP)   /* 2816 */

// k_all smem byte layout (dynamic) -- R10 known-good
#define SM_VS0 0                         /* V tf32 bits [128][40] = 20480 B */
#define SM_VS1 (SM_VS0 + 20480)
#define SM_HS  (SM_VS1 + 20480)          /* relu(a) tf32 bits [128][132] = 67584 B */
#define SM_C0  (SM_HS + 67584)           /* c16 stage 128*136 halfs = 34816 B */
#define SM_C1  (SM_C0 + 34816)
#define SM_RED (SM_C1 + 34816)           /* K-half reduce buf [128][40] f32 = 20480 B */
#define SM_TOT (SM_RED + 20480)          /* 198656 B */

// ONE extern dynamic-smem symbol for the whole TU
extern __shared__ __align__(16) char dyn_smem[];

// Scratch
__device__ __align__(16) float  g_S[(size_t)NC * BH];
__device__ __align__(16) float  g_P[(size_t)NC * BH];
__device__ __align__(16) float  g_part[(size_t)NSL * BL * 40];
__device__ __align__(16) __half g_c16[(size_t)Lsz * BH];

using u64 = unsigned long long;

__device__ __forceinline__ u64 splat2(float x) {
    u64 r; unsigned u = __float_as_uint(x);
    asm("mov.b64 %0, {%1, %1};" : "=l"(r) : "r"(u));
    return r;
}
__device__ __forceinline__ u64 fma2(u64 a, u64 b, u64 c) {
    u64 d; asm("fma.rn.f32x2 %0, %1, %2, %3;" : "=l"(d) : "l"(a), "l"(b), "l"(c));
    return d;
}
__device__ __forceinline__ u64 add2(u64 a, u64 b) {
    u64 d; asm("add.rn.f32x2 %0, %1, %2;" : "=l"(d) : "l"(a), "l"(b));
    return d;
}
__device__ __forceinline__ void cp16(unsigned dst, const void* src) {
    asm volatile("cp.async.ca.shared.global [%0], [%1], 16;" :: "r"(dst), "l"(src));
}
__device__ __forceinline__ void cp4(unsigned dst, const void* src) {
    asm volatile("cp.async.ca.shared.global [%0], [%1], 4;" :: "r"(dst), "l"(src));
}
__device__ __forceinline__ void cp_commit() { asm volatile("cp.async.commit_group;"); }
__device__ __forceinline__ void cp_wait0()  { asm volatile("cp.async.wait_group 0;"); }
__device__ __forceinline__ unsigned f2tf32(float x) {
    unsigned r; asm("cvt.rna.tf32.f32 %0, %1;" : "=r"(r) : "f"(x)); return r;
}
// m16n8k8 tf32 HMMA (plain sm_80+ PTX; valid on the harness's sm_103 target)
__device__ __forceinline__ void mma_tf32(float d[4],
                                         unsigned a0, unsigned a1, unsigned a2, unsigned a3,
                                         unsigned b0, unsigned b1) {
    asm volatile(
        "mma.sync.aligned.m16n8k8.row.col.f32.tf32.tf32.f32 "
        "{%0,%1,%2,%3}, {%4,%5,%6,%7}, {%8,%9}, {%0,%1,%2,%3};"
        : "+f"(d[0]), "+f"(d[1]), "+f"(d[2]), "+f"(d[3])
        : "r"(a0), "r"(a1), "r"(a2), "r"(a3), "r"(b0), "r"(b1));
}

// ---------------------------------------------------------------------------
// k_sums v2: 64-b tile, 2 blocks/SM (32 warps). Thread tile 2b x 8h.
// ---------------------------------------------------------------------------
__device__ __forceinline__ void stage_wx_async(unsigned ws_a, unsigned xs_a,
                                               const float* __restrict__ W,
                                               const float* __restrict__ inp,
                                               const float* __restrict__ zz,
                                               int l, int h0, int b0, int tid)
{
    const float4* wsrc = (const float4*)(W + (size_t)l * (Isz * Hsz)) + (h0 >> 2);
#pragma unroll
    for (int q = 0; q < 3; q++) {
        int idx = tid + NT * q;
        if (idx < Isz * 32) {
            int row = idx >> 5, col = idx & 31;
            cp16(ws_a + (unsigned)(row * 32 + col) * 16, wsrc + row * 128 + col);
        }
    }
    // z part: 64 rows x 8 float4 = 512 -> exactly one pass
    {
        int b = tid >> 3, qf = tid & 7;
        cp16(xs_a + (unsigned)(b * XP + 4 + qf * 4) * 4,
             zz + (size_t)(b0 + b) * (Lsz * Csz) + (size_t)l * Csz + qf * 4);
    }
    if (tid < BTS * Dsz) {
        int b = tid / Dsz, i = tid % Dsz;
        cp4(xs_a + (unsigned)(b * XP + i) * 4,
            inp + (size_t)(b0 + b) * (Lsz * Dsz) + (size_t)l * Dsz + i);
    }
}

__device__ __forceinline__ void encode_step(u64 c2[2][4], const float* ws,
                                            const float* xs, int bg, int hg)
{
#pragma unroll
    for (int r = 0; r < 2; r++)
#pragma unroll
        for (int p = 0; p < 4; p++) c2[r][p] = 0ull;
#pragma unroll
    for (int i = 0; i < Isz; i++) {
        const int xc = (i < Dsz) ? i : i + 1;
        u64 xa[2], wv[4];
#pragma unroll
        for (int r = 0; r < 2; r++) xa[r] = splat2(xs[(bg * 2 + r) * XP + xc]);
#pragma unroll
        for (int p = 0; p < 4; p++) wv[p] = *(const u64*)&ws[i * HS + hg * 2 + 32 * p];
#pragma unroll
        for (int r = 0; r < 2; r++)
#pragma unroll
            for (int p = 0; p < 4; p++) c2[r][p] = fma2(xa[r], wv[p], c2[r][p]);
    }
}

__global__ void __launch_bounds__(NT, 2) k_sums(const float* __restrict__ inp,
                                                const float* __restrict__ zz,
                                                const float* __restrict__ W)
{
    float* smem = (float*)dyn_smem;
    float* ws[2] = { smem, smem + WCNT };
    float* xs[2] = { smem + 2 * WCNT, smem + 2 * WCNT + XCNT };
    const unsigned sbase = (unsigned)__cvta_generic_to_shared(dyn_smem);
    const unsigned ws_a[2] = { sbase, sbase + WCNT * 4u };
    const unsigned xs_a[2] = { sbase + 2u * WCNT * 4u, sbase + (2u * WCNT + XCNT) * 4u };

    const int tid = threadIdx.x;
    const int b0  = (blockIdx.x / NSL) * BTS;
    const int h0  = (blockIdx.x % NSL) * HS;
    const int k   = blockIdx.y;
    const int bg  = tid >> 4, hg = tid & 15;   // 2b x 8h per thread

    u64 acc[2][4];
#pragma unroll
    for (int r = 0; r < 2; r++)
#pragma unroll
        for (int p = 0; p < 4; p++) acc[r][p] = 0ull;

    stage_wx_async(ws_a[0], xs_a[0], W, inp, zz, k * LC, h0, b0, tid);
    cp_commit(); cp_wait0();
    __syncthreads();

    for (int t = 0; t < LC; t++) {
        const int l = k * LC + t;
        const int cur = t & 1, nxt = cur ^ 1;
        if (t + 1 < LC) {
            stage_wx_async(ws_a[nxt], xs_a[nxt], W, inp, zz, l + 1, h0, b0, tid);
            cp_commit();
        }
        u64 c2[2][4];
        encode_step(c2, ws[cur], xs[cur], bg, hg);
#pragma unroll
        for (int r = 0; r < 2; r++) {
            __half* crow = g_c16 + ((size_t)l * Bsz + b0 + bg * 2 + r) * Hsz + h0;
#pragma unroll
            for (int p = 0; p < 4; p++) {
                acc[r][p] = add2(acc[r][p], c2[r][p]);
                float2 f = *(float2*)&c2[r][p];
                *(__half2*)&crow[hg * 2 + 32 * p] = __floats2half2_rn(f.x, f.y);
            }
        }
        cp_wait0();
        __syncthreads();
    }

    float* sb = g_S + (size_t)k * BH + (size_t)b0 * Hsz + h0;
#pragma unroll
    for (int r = 0; r < 2; r++)
#pragma unroll
        for (int p = 0; p < 4; p++)
            *(u64*)&sb[(size_t)(bg * 2 + r) * Hsz + hg * 2 + 32 * p] = acc[r][p];
}

__global__ void k_scan(const float* __restrict__ benc)
{
    const int idx = blockIdx.x * 256 + threadIdx.x;
    float run = benc[idx & (Hsz - 1)];
#pragma unroll 5
    for (int k = 0; k < NC; k++) {
        g_P[(size_t)k * BH + idx] = run;
        run += g_S[(size_t)k * BH + idx];
    }
}

// ---------------------------------------------------------------------------
// k_all: R10 known-good. prefix (registers, fed by staged c16) + HMMA tf32
// decode. Block = (btile*NSL + slice, chunk), 512 threads = 16 warps.
// ---------------------------------------------------------------------------
__global__ void __launch_bounds__(NT) k_all(const float* __restrict__ Vmu,
                                            const float* __restrict__ Vsg,
                                            const float* __restrict__ Vpi)
{
    char* smem = dyn_smem;
    const unsigned sbase = (unsigned)__cvta_generic_to_shared(dyn_smem);
    unsigned* vs_u[2] = { (unsigned*)(smem + SM_VS0), (unsigned*)(smem + SM_VS1) };
    unsigned* hs_u    = (unsigned*)(smem + SM_HS);
    __half*   cs[2]   = { (__half*)(smem + SM_C0), (__half*)(smem + SM_C1) };
    float*    redp    = (float*)(smem + SM_RED);
    const unsigned cs_a[2] = { sbase + SM_C0, sbase + SM_C1 };

    const int tid = threadIdx.x;
    const int wid = tid >> 5, lane = tid & 31;
    const int b0  = (blockIdx.x / NSL) * BT;
    const int s   = blockIdx.x % NSL;
    const int h0  = s * HS;
    const int k   = blockIdx.y;
    const int bg  = tid >> 4, hg = tid & 15;   // acc owner: 4b x 8h
    const int sb  = wid & 7;                   // b strip (16 rows)
    const int kh  = wid >> 3;                  // K half (64 h)
    const int rbase = sb * 16 + (lane >> 2);
    const int kl  = lane & 3;

    unsigned vq[10], bdst[10];
#pragma unroll
    for (int q = 0; q < 10; q++) {
        int u = tid + NT * q;
        int h = u / 40, jc = u % 40;
        unsigned tag, off;
        if (jc < 15)      { tag = 0u; off = (h0 + h) * Osz + jc; }
        else if (jc < 30) { tag = 1u; off = (h0 + h) * Osz + (jc - 15); }
        else if (jc < 35) { tag = 2u; off = (h0 + h) * Msz + (jc - 30); }
        else              { tag = 3u; off = 0; }
        vq[q] = (tag << 30) | off;
        bdst[q] = (unsigned)(h * 40 + jc);
    }

    auto load_V = [&](int l, unsigned vreg[10]) {
        const size_t lmu = (size_t)l * (Hsz * Osz);
        const size_t lpi = (size_t)l * (Hsz * Msz);
#pragma unroll
        for (int q = 0; q < 10; q++) {
            unsigned tag = vq[q] >> 30, off = vq[q] & 0x3FFFFFFFu;
            float v = 0.0f;
            if (tag == 0u)      v = Vmu[lmu + off];
            else if (tag == 1u) v = Vsg[lmu + off];
            else if (tag == 2u) v = Vpi[lpi + off];
            vreg[q] = f2tf32(v);
        }
    };
    auto stage_c = [&](int l, unsigned ca) {
#pragma unroll
        for (int q = 0; q < 4; q++) {
            int idx = tid + NT * q;
            int row = idx >> 4, ch = idx & 15;
            cp16(ca + (unsigned)(row * CP + ch * 8) * 2,
                 g_c16 + ((size_t)l * Bsz + b0 + row) * Hsz + h0 + ch * 8);
        }
        cp_commit();
    };
    auto publish_A = [&](u64 acc[4][4]) {
#pragma unroll
        for (int r = 0; r < 4; r++) {
            const int b = bg * 4 + r;
#pragma unroll
            for (int p = 0; p < 4; p++) {
                float2 v = *(float2*)&acc[r][p];
                unsigned lo = f2tf32(fmaxf(v.x, 0.0f));
                unsigned hi = f2tf32(fmaxf(v.y, 0.0f));
                u64 pk; asm("mov.b64 %0, {%1, %2};" : "=l"(pk) : "r"(lo), "r"(hi));
                *(u64*)&hs_u[b * HP2 + hg * 2 + 32 * p] = pk;
            }
        }
    };

    // prologue
    stage_c(k * LC, cs_a[0]);
    {
        unsigned v0[10];
        load_V(k * LC, v0);
#pragma unroll
        for (int q = 0; q < 10; q++) vs_u[0][bdst[q]] = v0[q];
    }
    u64 acc[4][4];
    {
        const float* P = g_P + (size_t)k * BH + (size_t)b0 * Hsz + h0;
#pragma unroll
        for (int r = 0; r < 4; r++)
#pragma unroll
            for (int p = 0; p < 4; p++) {
                float2 v = *(const float2*)&P[(size_t)(bg * 4 + r) * Hsz + hg * 2 + 32 * p];
                acc[r][p] = *(const u64*)&v;
            }
    }
    publish_A(acc);
    cp_wait0();
    __syncthreads();

    for (int t = 0; t < LC; t++) {
        const int l = k * LC + t;
        const int cur = t & 1, nxt = cur ^ 1;

        unsigned vreg[10];
        if (t + 1 < LC) {
            stage_c(l + 1, cs_a[nxt]);
            load_V(l + 1, vreg);
        }

        float d[5][4];
#pragma unroll
        for (int n = 0; n < 5; n++)
#pragma unroll
            for (int u = 0; u < 4; u++) d[n][u] = 0.0f;

        const unsigned* vcur = vs_u[cur];
#pragma unroll
        for (int kc = 0; kc < 8; kc++) {
            const int k0 = kh * 64 + kc * 8;
            unsigned a0 = hs_u[rbase * HP2 + k0 + kl];
            unsigned a1 = hs_u[(rbase + 8) * HP2 + k0 + kl];
            unsigned a2 = hs_u[rbase * HP2 + k0 + 4 + kl];
            unsigned a3 = hs_u[(rbase + 8) * HP2 + k0 + 4 + kl];
#pragma unroll
            for (int n = 0; n < 5; n++) {
                unsigned bf0 = vcur[(k0 + kl) * 40 + n * 8 + (lane >> 2)];
                unsigned bf1 = vcur[(k0 + 4 + kl) * 40 + n * 8 + (lane >> 2)];
                mma_tf32(d[n], a0, a1, a2, a3, bf0, bf1);
            }
        }

        if (kh) {
#pragma unroll
            for (int n = 0; n < 5; n++) {
                *(float2*)&redp[rbase * 40 + n * 8 + 2 * kl]       = make_float2(d[n][0], d[n][1]);
                *(float2*)&redp[(rbase + 8) * 40 + n * 8 + 2 * kl] = make_float2(d[n][2], d[n][3]);
            }
        }

        {
            const __half* cb = cs[cur];
#pragma unroll
            for (int r = 0; r < 4; r++)
#pragma unroll
                for (int p = 0; p < 4; p++) {
                    __half2 h2 = *(const __half2*)&cb[(bg * 4 + r) * CP + hg * 2 + 32 * p];
                    float2 c = __half22float2(h2);
                    float2 a = *(float2*)&acc[r][p];
                    a.x += c.x; a.y += c.y;
                    acc[r][p] = *(u64*)&a;
                }
        }

        __syncthreads();

        if (!kh) {
            float* dstb = g_part + ((size_t)s * BL + (size_t)l * Bsz + b0) * 40;
#pragma unroll
            for (int n = 0; n < 5; n++) {
                const int j = n * 8 + 2 * kl;
                float2 r0 = *(float2*)&redp[rbase * 40 + j];
                float2 r1 = *(float2*)&redp[(rbase + 8) * 40 + j];
                *(float2*)&dstb[(size_t)rbase * 40 + j] =
                    make_float2(d[n][0] + r0.x, d[n][1] + r0.y);
                *(float2*)&dstb[(size_t)(rbase + 8) * 40 + j] =
                    make_float2(d[n][2] + r1.x, d[n][3] + r1.y);
            }
        }

        publish_A(acc);
        if (t + 1 < LC) {
#pragma unroll
            for (int q = 0; q < 10; q++) vs_u[nxt][bdst[q]] = vreg[q];
            cp_wait0();
        }
        __syncthreads();
    }
}

// ---------------------------------------------------------------------------
// k_reduce: sum slices + output biases. g_part layout [s][l*B + b][40].
// ---------------------------------------------------------------------------
__global__ void __launch_bounds__(280) k_reduce(const float* __restrict__ bmu,
                                                const float* __restrict__ bsg,
                                                const float* __restrict__ bpi,
                                                float* __restrict__ out)
{
    const int p = threadIdx.x / 35;
    const int j = threadIdx.x % 35;
    const size_t pr = (size_t)blockIdx.x * 8 + p;
    const int l = (int)(pr >> 8);
    const int b = (int)(pr & 255);

    float v = 0.0f;
#pragma unroll
    for (int s = 0; s < NSL; s++)
        v += g_part[((size_t)s * BL + pr) * 40 + j];

    float bias;
    if (j < 15)      bias = bmu[l * Osz + j];
    else if (j < 30) bias = bsg[l * Osz + (j - 15)];
    else             bias = bpi[l * Msz + (j - 30)];

    out[((size_t)b * Lsz + l) * Jsz + j] = v + bias;
}

// ---------------------------------------------------------------------------
extern "C" void kernel_launch(void* const* d_in, const int* in_sizes, int n_in,
                              void* d_out, int out_size)
{
    const float* inp  = (const float*)d_in[0];
    const float* zz   = (const float*)d_in[1];
    const float* W    = (const float*)d_in[2];
    const float* benc = (const float*)d_in[3];
    const float* Vmu  = (const float*)d_in[4];
    const float* bmu  = (const float*)d_in[5];
    const float* Vsg  = (const float*)d_in[6];
    const float* bsg  = (const float*)d_in[7];
    const float* Vpi  = (const float*)d_in[8];
    const float* bpi  = (const float*)d_in[9];
    float* out = (float*)d_out;

    const int sm1 = (2 * WCNT + 2 * XCNT) * (int)sizeof(float);   // 58.4 KB
    cudaFuncSetAttribute(k_sums, cudaFuncAttributeMaxDynamicSharedMemorySize, sm1);
    cudaFuncSetAttribute(k_all,  cudaFuncAttributeMaxDynamicSharedMemorySize, SM_TOT);

    k_sums<<<dim3(NBTS * NSL, NC), NT, sm1>>>(inp, zz, W);
    k_scan<<<BH / 256, 256>>>(benc);
    k_all <<<dim3(NBT * NSL, NC), NT, SM_TOT>>>(Vmu, Vsg, Vpi);
    k_reduce<<<BL / 8, 280>>>(bmu, bsg, bpi, out);
}